// round 16
// baseline (speedup 1.0000x reference)
#include <cuda_runtime.h>
#include <math.h>

#define BB 64
#define HH 1024
#define INN 1024
#define GN_EPS 1e-5f

#define NTILE 32      // n per block
#define SPLITS 4
#define KSP 256       // K per split
#define KCc 32        // smem K chunk
#define CH_ITERS (KSP / KCc)
#define NG (6 * HH)   // 6144 fused gate columns

// Scratch (all small; partials live in the out_C output region)
__device__ float g_gate[6][BB * HH];          // q,k,v,i,f,o
__device__ float g_ht[BB * HH];
__device__ float g_denom[BB];
__device__ float g_vq[BB];
__device__ unsigned int g_cnt[BB];            // zero-init; self-resetting
__device__ unsigned int g_xh[BB * INN];       // x tf32 hi (256 KB)
__device__ unsigned int g_xl[BB * INN];       // x tf32 lo (256 KB)

__device__ __forceinline__ float sigmoidf_(float x) {
    return 1.0f / (1.0f + expf(-x));
}
__device__ __forceinline__ float softplusf_(float x) {
    return fmaxf(x, 0.0f) + log1pf(expf(-fabsf(x)));
}

__device__ __forceinline__ unsigned int cvt1_(float v) {
    unsigned int h;
    asm("cvt.rna.tf32.f32 %0, %1;" : "=r"(h) : "f"(v));
    return h;
}

#define MMA_TF32(c, a0, a1, a2, a3, b0, b1)                                 \
    asm("mma.sync.aligned.m16n8k8.row.col.f32.tf32.tf32.f32 "               \
        "{%0,%1,%2,%3}, {%4,%5,%6,%7}, {%8,%9}, {%0,%1,%2,%3};"             \
        : "+f"(c[0]), "+f"(c[1]), "+f"(c[2]), "+f"(c[3])                    \
        : "r"(a0), "r"(a1), "r"(a2), "r"(a3), "r"(b0), "r"(b1))

// ----------------------------------------------------------------------------
// Kernel 0: split x into tf32 hi/lo once (exact-x decomposition), 4 elem/thread.
// ----------------------------------------------------------------------------
__global__ __launch_bounds__(256) void k0_xsplit(const float* __restrict__ x)
{
    const int i4 = (blockIdx.x * 256 + threadIdx.x) * 4;   // 64K elements total
    const float4 v = *(const float4*)(x + i4);
    const float vv[4] = {v.x, v.y, v.z, v.w};
    uint4 h4, l4;
    unsigned int* hp = &h4.x;
    unsigned int* lp = &l4.x;
#pragma unroll
    for (int c = 0; c < 4; c++) {
        const unsigned int h = cvt1_(vv[c]);
        const float r = vv[c] - __uint_as_float(h);
        hp[c] = h;
        lp[c] = cvt1_(r);
    }
    *(uint4*)(g_xh + i4) = h4;
    *(uint4*)(g_xl + i4) = l4;
}

// ----------------------------------------------------------------------------
// Kernel 1: fused split-K GEMM over all six gates, tf32 tensor cores.
// 2xTF32 with exact x (pre-split hi/lo; W rounded to tf32 hi only).
// part[sp][b][ng] = sum_{k in split sp} x[b,k] * W_all[ng,k], ng in [0,6144).
// Tile 64m x 32n, K=256 per split, 128 threads (4 warps, each 16m x 32n).
// grid = (192 n-blocks, 4 splits) = 768 blocks.
// ----------------------------------------------------------------------------
__global__ __launch_bounds__(128) void k1_gemm_gates(
    const float* __restrict__ Wq, const float* __restrict__ Wk,
    const float* __restrict__ Wv, const float* __restrict__ Wi,
    const float* __restrict__ Wf, const float* __restrict__ Wo,
    float* __restrict__ part)   // [SPLITS][BB][NG]
{
    const int n0g = blockIdx.x * NTILE;    // tile never straddles a gate (1024/32=32)
    const int g = n0g >> 10;
    const int nloc0 = n0g & 1023;
    const float* __restrict__ W =
        (g == 0) ? Wq : (g == 1) ? Wk : (g == 2) ? Wv : (g == 3) ? Wi : (g == 4) ? Wf : Wo;
    const int k0s = blockIdx.y * KSP;

    // [row][k] layouts, stride 36 floats (144B: 16B-aligned, conflict-free frags)
    __shared__ __align__(16) unsigned int Xh[64][36], Xl[64][36];
    __shared__ __align__(16) unsigned int Wh[32][36];

    const int tid = threadIdx.x;
    const int warp = tid >> 5;
    const int lane = tid & 31;
    const int gid = lane >> 2;     // 0..7
    const int tig = lane & 3;      // 0..3

    // loader indices: X 512 uint4 per array (4/thread), W 256 float4 (2/thread)
    const int xm[4] = { tid >> 3, (tid + 128) >> 3, (tid + 256) >> 3, (tid + 384) >> 3 };
    const int lkq = (tid & 7) * 4;

    float acc[4][4];   // [ntile][c0..c3]
#pragma unroll
    for (int i = 0; i < 4; i++)
#pragma unroll
        for (int j = 0; j < 4; j++) acc[i][j] = 0.0f;

    // prefetch chunk 0
    uint4 xah[4], xal[4];
    float4 wa[2];
#pragma unroll
    for (int i = 0; i < 4; i++) {
        xah[i] = *(const uint4*)(g_xh + xm[i] * INN + k0s + lkq);
        xal[i] = *(const uint4*)(g_xl + xm[i] * INN + k0s + lkq);
    }
#pragma unroll
    for (int i = 0; i < 2; i++)
        wa[i] = *(const float4*)(W + (size_t)(nloc0 + xm[i]) * INN + k0s + lkq);

#pragma unroll
    for (int it = 0; it < CH_ITERS; it++) {
        __syncthreads();
#pragma unroll
        for (int i = 0; i < 4; i++) {
            *(uint4*)&Xh[xm[i]][lkq] = xah[i];
            *(uint4*)&Xl[xm[i]][lkq] = xal[i];
        }
#pragma unroll
        for (int i = 0; i < 2; i++) {
            uint4 hw;
            hw.x = cvt1_(wa[i].x); hw.y = cvt1_(wa[i].y);
            hw.z = cvt1_(wa[i].z); hw.w = cvt1_(wa[i].w);
            *(uint4*)&Wh[xm[i]][lkq] = hw;
        }
        __syncthreads();

        // prefetch next chunk (overlaps the mma loop)
        if (it + 1 < CH_ITERS) {
            const int k0 = k0s + (it + 1) * KCc;
#pragma unroll
            for (int i = 0; i < 4; i++) {
                xah[i] = *(const uint4*)(g_xh + xm[i] * INN + k0 + lkq);
                xal[i] = *(const uint4*)(g_xl + xm[i] * INN + k0 + lkq);
            }
#pragma unroll
            for (int i = 0; i < 2; i++)
                wa[i] = *(const float4*)(W + (size_t)(nloc0 + xm[i]) * INN + k0 + lkq);
        }

#pragma unroll
        for (int ks = 0; ks < KCc / 8; ks++) {
            const int kb = ks * 8;
            const int r0 = warp * 16 + gid;
            // A fragments (PTX m16n8k8 tf32 mapping)
            const unsigned int a0h = Xh[r0][kb + tig];
            const unsigned int a1h = Xh[r0 + 8][kb + tig];
            const unsigned int a2h = Xh[r0][kb + tig + 4];
            const unsigned int a3h = Xh[r0 + 8][kb + tig + 4];
            const unsigned int a0l = Xl[r0][kb + tig];
            const unsigned int a1l = Xl[r0 + 8][kb + tig];
            const unsigned int a2l = Xl[r0][kb + tig + 4];
            const unsigned int a3l = Xl[r0 + 8][kb + tig + 4];
#pragma unroll
            for (int nt = 0; nt < 4; nt++) {
                const int nr = nt * 8 + gid;
                const unsigned int b0h = Wh[nr][kb + tig];
                const unsigned int b1h = Wh[nr][kb + tig + 4];
                MMA_TF32(acc[nt], a0h, a1h, a2h, a3h, b0h, b1h);
                MMA_TF32(acc[nt], a0l, a1l, a2l, a3l, b0h, b1h);
            }
        }
    }

    // epilogue: C fragment rows gid / gid+8, cols 2*tig, 2*tig+1
    float* __restrict__ po = part + (size_t)blockIdx.y * BB * NG;
    const int r0 = warp * 16 + gid;
    const int r1 = r0 + 8;
#pragma unroll
    for (int nt = 0; nt < 4; nt++) {
        const int col = n0g + nt * 8 + 2 * tig;
        *(float2*)(po + (size_t)r0 * NG + col) = make_float2(acc[nt][0], acc[nt][1]);
        *(float2*)(po + (size_t)r1 * NG + col) = make_float2(acc[nt][2], acc[nt][3]);
    }
}

// ----------------------------------------------------------------------------
// Kernel 2: combine split-K partials (fixed order => deterministic), apply
// bias + activations, store gates; then n/m update + denom/vq reductions.
// grid = 64 (batch), block = 1024.
// ----------------------------------------------------------------------------
__global__ __launch_bounds__(1024) void k2_combine_nm(
    const float* __restrict__ part,
    const float* __restrict__ bi, const float* __restrict__ bf,
    const float* __restrict__ bo,
    const float* __restrict__ n_prev, const float* __restrict__ m_prev,
    float* __restrict__ out_n, float* __restrict__ out_m)
{
    const int b = blockIdx.x;
    const int tid = threadIdx.x;
    const int h = b * HH + tid;

    float y[6];
#pragma unroll
    for (int g = 0; g < 6; g++) {
        float s = 0.0f;
#pragma unroll
        for (int sp = 0; sp < SPLITS; sp++)
            s += part[((size_t)sp * BB + b) * NG + g * HH + tid];
        y[g] = s;
    }

    const float qv = y[0];
    const float kv = y[1];
    const float vv = y[2];
    const float iv = softplusf_(y[3] + bi[tid]);
    const float fv = sigmoidf_(y[4] + bf[tid]);
    const float ov = sigmoidf_(y[5] + bo[tid]);

    g_gate[0][h] = qv;
    g_gate[1][h] = kv;
    g_gate[2][h] = vv;
    g_gate[3][h] = iv;
    g_gate[4][h] = fv;
    g_gate[5][h] = ov;

    const float nv = fmaf(fv, n_prev[h], iv * kv);
    const float mv = fmaxf(fv * m_prev[h], iv);
    out_n[h] = nv;
    out_m[h] = mv;

    float snq = nv * qv;
    float svq = vv * qv;
#pragma unroll
    for (int s = 16; s > 0; s >>= 1) {
        snq += __shfl_xor_sync(0xFFFFFFFFu, snq, s);
        svq += __shfl_xor_sync(0xFFFFFFFFu, svq, s);
    }
    __shared__ float p1[32], p2[32];
    const int warp = tid >> 5, lane = tid & 31;
    if (lane == 0) { p1[warp] = snq; p2[warp] = svq; }
    __syncthreads();
    if (warp == 0) {
        float a = p1[lane], c = p2[lane];
#pragma unroll
        for (int s = 16; s > 0; s >>= 1) {
            a += __shfl_xor_sync(0xFFFFFFFFu, a, s);
            c += __shfl_xor_sync(0xFFFFFFFFu, c, s);
        }
        if (lane == 0) {
            g_denom[b] = fmaxf(a, 1.0f);
            g_vq[b] = c;
        }
    }
}

// ----------------------------------------------------------------------------
// Kernel 3: streaming 512 MB + fused GroupNorm epilogue (last block per batch)
// grid = (64 rowblocks, 64 b), block = 512 (16 warps, 1 warp/row)
// Overwrites ALL of out_C (including the region k1 used as scratch).
// ----------------------------------------------------------------------------
__global__ __launch_bounds__(512) void k3_c_update(
    const float* __restrict__ C_prev, float* __restrict__ out_C,
    const float* __restrict__ gn_w, const float* __restrict__ gn_b,
    float* __restrict__ out_h)
{
    const int b = blockIdx.y;
    const int r0 = blockIdx.x * 16;
    const int tid = threadIdx.x;

    __shared__ float sq[HH];
    __shared__ float sv[HH];
#pragma unroll
    for (int j = 0; j < 2; j++) {
        const int idx = tid + j * 512;
        sq[idx] = g_gate[0][b * HH + idx];
        sv[idx] = g_gate[2][b * HH + idx];
    }
    __syncthreads();

    const int warp = tid >> 5;
    const int lane = tid & 31;
    const int r = r0 + warp;

    const float f  = g_gate[4][b * HH + r];
    const float ik = g_gate[3][b * HH + r] * g_gate[1][b * HH + r];

    const float* __restrict__ cp = C_prev + ((size_t)b * HH + r) * HH;
    float* __restrict__ co = out_C + ((size_t)b * HH + r) * HH;

    float4 p[8];
#pragma unroll
    for (int j = 0; j < 8; j++)
        p[j] = __ldcs((const float4*)(cp + lane * 4 + j * 128));

    float dot = 0.0f;
#pragma unroll
    for (int j = 0; j < 8; j++) {
        const int c = lane * 4 + j * 128;
        float4 vv = *(const float4*)(sv + c);
        float4 qq = *(const float4*)(sq + c);
        float4 o;
        o.x = fmaf(f, p[j].x, ik * vv.x);
        o.y = fmaf(f, p[j].y, ik * vv.y);
        o.z = fmaf(f, p[j].z, ik * vv.z);
        o.w = fmaf(f, p[j].w, ik * vv.w);
        __stcs((float4*)(co + c), o);
        dot = fmaf(p[j].x, qq.x, dot);
        dot = fmaf(p[j].y, qq.y, dot);
        dot = fmaf(p[j].z, qq.z, dot);
        dot = fmaf(p[j].w, qq.w, dot);
    }
#pragma unroll
    for (int s = 16; s > 0; s >>= 1)
        dot += __shfl_xor_sync(0xFFFFFFFFu, dot, s);
    if (lane == 0) {
        g_ht[b * HH + r] = fmaf(f, dot, ik * g_vq[b]);
        __threadfence();
    }

    // ---- last-block-per-batch GroupNorm epilogue ----
    __syncthreads();
    __shared__ unsigned int s_old;
    if (tid == 0)
        s_old = atomicAdd(&g_cnt[b], 1u);
    __syncthreads();
    if (s_old != 63u) return;

    __threadfence();
    const float inv_d = 1.0f / g_denom[b];

    float xv[2];
    float s = 0.0f, s2 = 0.0f;
#pragma unroll
    for (int j = 0; j < 2; j++) {
        const int h = tid + j * 512;
        const float v = __ldcg(&g_ht[b * HH + h]) * inv_d;
        xv[j] = v;
        s += v;
        s2 = fmaf(v, v, s2);
    }
#pragma unroll
    for (int st = 16; st > 0; st >>= 1) {
        s  += __shfl_xor_sync(0xFFFFFFFFu, s, st);
        s2 += __shfl_xor_sync(0xFFFFFFFFu, s2, st);
    }
    __shared__ float p1[16], p2[16];
    __shared__ float mu_s, rstd_s;
    if (lane == 0) { p1[warp] = s; p2[warp] = s2; }
    __syncthreads();
    if (warp == 0) {
        float a = (lane < 16) ? p1[lane] : 0.0f;
        float c = (lane < 16) ? p2[lane] : 0.0f;
#pragma unroll
        for (int st = 8; st > 0; st >>= 1) {
            a += __shfl_xor_sync(0xFFFFFFFFu, a, st);
            c += __shfl_xor_sync(0xFFFFFFFFu, c, st);
        }
        if (lane == 0) {
            const float mu = a * (1.0f / HH);
            float var = c * (1.0f / HH) - mu * mu;
            var = fmaxf(var, 0.0f);
            mu_s = mu;
            rstd_s = rsqrtf(var + GN_EPS);
        }
    }
    __syncthreads();
    const float mu = mu_s, rstd = rstd_s;

#pragma unroll
    for (int j = 0; j < 2; j++) {
        const int h = tid + j * 512;
        const float norm = fmaf((xv[j] - mu) * rstd, gn_w[h], gn_b[h]);
        out_h[b * HH + h] = g_gate[5][b * HH + h] * norm;
    }
    if (tid == 0) g_cnt[b] = 0u;
}

// ----------------------------------------------------------------------------
extern "C" void kernel_launch(void* const* d_in, const int* in_sizes, int n_in,
                              void* d_out, int out_size)
{
    const float* x      = (const float*)d_in[0];
    const float* C_prev = (const float*)d_in[1];
    const float* n_prev = (const float*)d_in[2];
    const float* m_prev = (const float*)d_in[3];
    const float* Wq     = (const float*)d_in[4];
    const float* Wk     = (const float*)d_in[5];
    const float* Wv     = (const float*)d_in[6];
    const float* Wi     = (const float*)d_in[7];
    const float* bi     = (const float*)d_in[8];
    const float* Wf     = (const float*)d_in[9];
    const float* bf     = (const float*)d_in[10];
    const float* Wo     = (const float*)d_in[11];
    const float* bo     = (const float*)d_in[12];
    const float* gn_w   = (const float*)d_in[13];
    const float* gn_b   = (const float*)d_in[14];

    float* out   = (float*)d_out;
    float* out_h = out;                                   // [B,H]
    float* out_C = out_h + BB * HH;                       // [B,H,H]
    float* out_n = out_C + (size_t)BB * HH * HH;          // [B,H]
    float* out_m = out_n + BB * HH;                       // [B,H]

    // Split-K partials live in the front of out_C (6.3 MB of its 256 MB);
    // k3 fully overwrites out_C afterwards, so this is pure scratch reuse.
    float* part = out_C;

    k0_xsplit<<<(BB * INN) / 1024, 256>>>(x);
    dim3 g1(NG / NTILE, SPLITS);     // (192, 4)
    k1_gemm_gates<<<g1, 128>>>(Wq, Wk, Wv, Wi, Wf, Wo, part);
    k2_combine_nm<<<BB, 1024>>>(part, bi, bf, bo, n_prev, m_prev, out_n, out_m);
    dim3 g3(HH / 16, BB);
    k3_c_update<<<g3, 512>>>(C_prev, out_C, gn_w, gn_b, out_h);
}

// round 17
// speedup vs baseline: 1.0470x; 1.0470x over previous
#include <cuda_runtime.h>
#include <math.h>

#define BB 64
#define HH 1024
#define INN 1024
#define GN_EPS 1e-5f

#define NTILE 64      // n per block
#define SPLITS 4
#define KSP 256       // K per split
#define KCc 32        // smem K chunk
#define CH_ITERS (KSP / KCc)
#define NG (6 * HH)   // 6144 fused gate columns

// Small scratch only (partials live in the out_C output region, overwritten by k3)
__device__ float g_gate[6][BB * HH];          // q,k,v,i,f,o
__device__ float g_ht[BB * HH];
__device__ float g_denom[BB];
__device__ float g_vq[BB];
__device__ unsigned int g_cnt[BB];            // zero-init; self-resetting

__device__ __forceinline__ float sigmoidf_(float x) {
    return 1.0f / (1.0f + expf(-x));
}
__device__ __forceinline__ float softplusf_(float x) {
    return fmaxf(x, 0.0f) + log1pf(expf(-fabsf(x)));
}

// split float into tf32 hi + tf32 lo (exact-x decomposition)
__device__ __forceinline__ void cvt2_(float v, unsigned int& h, unsigned int& l) {
    asm("cvt.rna.tf32.f32 %0, %1;" : "=r"(h) : "f"(v));
    float r = v - __uint_as_float(h);
    asm("cvt.rna.tf32.f32 %0, %1;" : "=r"(l) : "f"(r));
}
__device__ __forceinline__ unsigned int cvt1_(float v) {
    unsigned int h;
    asm("cvt.rna.tf32.f32 %0, %1;" : "=r"(h) : "f"(v));
    return h;
}

#define MMA_TF32(c, a0, a1, a2, a3, b0, b1)                                 \
    asm("mma.sync.aligned.m16n8k8.row.col.f32.tf32.tf32.f32 "               \
        "{%0,%1,%2,%3}, {%4,%5,%6,%7}, {%8,%9}, {%0,%1,%2,%3};"             \
        : "+f"(c[0]), "+f"(c[1]), "+f"(c[2]), "+f"(c[3])                    \
        : "r"(a0), "r"(a1), "r"(a2), "r"(a3), "r"(b0), "r"(b1))

// ----------------------------------------------------------------------------
// Kernel 1: fused split-K GEMM over all six gates, tf32 tensor cores.
// 2xTF32 with exact x (x split hi/lo in-kernel; W rounded to tf32 hi only).
// part[sp][b][ng] = sum_{k in split sp} x[b,k] * W_all[ng,k], ng in [0,6144).
// Tile 64m x 64n, K=256 per split, 256 threads (8 warps as 4m x 2n;
// each warp 16m x 32n — identical inner loop to the proven R15 config).
// grid = (96 n-blocks, 4 splits) = 384 blocks.
// ----------------------------------------------------------------------------
__global__ __launch_bounds__(256) void k1_gemm_gates(
    const float* __restrict__ x,
    const float* __restrict__ Wq, const float* __restrict__ Wk,
    const float* __restrict__ Wv, const float* __restrict__ Wi,
    const float* __restrict__ Wf, const float* __restrict__ Wo,
    float* __restrict__ part)   // [SPLITS][BB][NG]
{
    const int n0g = blockIdx.x * NTILE;    // tile never straddles a gate (1024/64=16)
    const int g = n0g >> 10;
    const int nloc0 = n0g & 1023;
    const float* __restrict__ W =
        (g == 0) ? Wq : (g == 1) ? Wk : (g == 2) ? Wv : (g == 3) ? Wi : (g == 4) ? Wf : Wo;
    const int k0s = blockIdx.y * KSP;

    // [row][k] layouts, stride 36 floats (144B: 16B-aligned, conflict-free frags)
    __shared__ __align__(16) unsigned int Xh[64][36], Xl[64][36];
    __shared__ __align__(16) unsigned int Wh[64][36];

    const int tid = threadIdx.x;
    const int warp = tid >> 5;
    const int lane = tid & 31;
    const int gid = lane >> 2;     // 0..7
    const int tig = lane & 3;      // 0..3
    const int warpm = warp & 3;    // 4 m-groups of 16 rows
    const int warpn = warp >> 2;   // 2 n-halves of 32 cols

    // loaders: X 64 rows x 8 float4-chunks = 512 chunks, 2/thread; W same
    const int xm[2] = { tid >> 3, (tid + 256) >> 3 };
    const int lkq = (tid & 7) * 4;

    float acc[4][4];   // [ntile][c0..c3]
#pragma unroll
    for (int i = 0; i < 4; i++)
#pragma unroll
        for (int j = 0; j < 4; j++) acc[i][j] = 0.0f;

    // prefetch chunk 0
    float4 xa[2], wa[2];
#pragma unroll
    for (int i = 0; i < 2; i++) {
        xa[i] = *(const float4*)(x + xm[i] * INN + k0s + lkq);
        wa[i] = *(const float4*)(W + (size_t)(nloc0 + xm[i]) * INN + k0s + lkq);
    }

#pragma unroll
    for (int it = 0; it < CH_ITERS; it++) {
        __syncthreads();
#pragma unroll
        for (int i = 0; i < 2; i++) {
            const float vx[4] = {xa[i].x, xa[i].y, xa[i].z, xa[i].w};
#pragma unroll
            for (int c = 0; c < 4; c++) {
                unsigned int h, l;
                cvt2_(vx[c], h, l);
                Xh[xm[i]][lkq + c] = h;
                Xl[xm[i]][lkq + c] = l;
            }
            const float vw[4] = {wa[i].x, wa[i].y, wa[i].z, wa[i].w};
#pragma unroll
            for (int c = 0; c < 4; c++)
                Wh[xm[i]][lkq + c] = cvt1_(vw[c]);
        }
        __syncthreads();

        // prefetch next chunk (overlaps the mma loop)
        if (it + 1 < CH_ITERS) {
            const int k0 = k0s + (it + 1) * KCc;
#pragma unroll
            for (int i = 0; i < 2; i++) {
                xa[i] = *(const float4*)(x + xm[i] * INN + k0 + lkq);
                wa[i] = *(const float4*)(W + (size_t)(nloc0 + xm[i]) * INN + k0 + lkq);
            }
        }

#pragma unroll
        for (int ks = 0; ks < KCc / 8; ks++) {
            const int kb = ks * 8;
            const int r0 = warpm * 16 + gid;
            // A fragments (PTX m16n8k8 tf32 mapping)
            const unsigned int a0h = Xh[r0][kb + tig];
            const unsigned int a1h = Xh[r0 + 8][kb + tig];
            const unsigned int a2h = Xh[r0][kb + tig + 4];
            const unsigned int a3h = Xh[r0 + 8][kb + tig + 4];
            const unsigned int a0l = Xl[r0][kb + tig];
            const unsigned int a1l = Xl[r0 + 8][kb + tig];
            const unsigned int a2l = Xl[r0][kb + tig + 4];
            const unsigned int a3l = Xl[r0 + 8][kb + tig + 4];
#pragma unroll
            for (int nt = 0; nt < 4; nt++) {
                const int nr = warpn * 32 + nt * 8 + gid;
                const unsigned int b0h = Wh[nr][kb + tig];
                const unsigned int b1h = Wh[nr][kb + tig + 4];
                MMA_TF32(acc[nt], a0h, a1h, a2h, a3h, b0h, b1h);
                MMA_TF32(acc[nt], a0l, a1l, a2l, a3l, b0h, b1h);
            }
        }
    }

    // epilogue: C fragment rows gid / gid+8, cols 2*tig, 2*tig+1
    float* __restrict__ po = part + (size_t)blockIdx.y * BB * NG;
    const int r0 = warpm * 16 + gid;
    const int r1 = r0 + 8;
#pragma unroll
    for (int nt = 0; nt < 4; nt++) {
        const int col = n0g + warpn * 32 + nt * 8 + 2 * tig;
        *(float2*)(po + (size_t)r0 * NG + col) = make_float2(acc[nt][0], acc[nt][1]);
        *(float2*)(po + (size_t)r1 * NG + col) = make_float2(acc[nt][2], acc[nt][3]);
    }
}

// ----------------------------------------------------------------------------
// Kernel 2: combine split-K partials (fixed order => deterministic), apply
// bias + activations, store gates; then n/m update + denom/vq reductions.
// grid = 64 (batch), block = 1024.
// ----------------------------------------------------------------------------
__global__ __launch_bounds__(1024) void k2_combine_nm(
    const float* __restrict__ part,
    const float* __restrict__ bi, const float* __restrict__ bf,
    const float* __restrict__ bo,
    const float* __restrict__ n_prev, const float* __restrict__ m_prev,
    float* __restrict__ out_n, float* __restrict__ out_m)
{
    const int b = blockIdx.x;
    const int tid = threadIdx.x;
    const int h = b * HH + tid;

    float y[6];
#pragma unroll
    for (int g = 0; g < 6; g++) {
        float s = 0.0f;
#pragma unroll
        for (int sp = 0; sp < SPLITS; sp++)
            s += part[((size_t)sp * BB + b) * NG + g * HH + tid];
        y[g] = s;
    }

    const float qv = y[0];
    const float kv = y[1];
    const float vv = y[2];
    const float iv = softplusf_(y[3] + bi[tid]);
    const float fv = sigmoidf_(y[4] + bf[tid]);
    const float ov = sigmoidf_(y[5] + bo[tid]);

    g_gate[0][h] = qv;
    g_gate[1][h] = kv;
    g_gate[2][h] = vv;
    g_gate[3][h] = iv;
    g_gate[4][h] = fv;
    g_gate[5][h] = ov;

    const float nv = fmaf(fv, n_prev[h], iv * kv);
    const float mv = fmaxf(fv * m_prev[h], iv);
    out_n[h] = nv;
    out_m[h] = mv;

    float snq = nv * qv;
    float svq = vv * qv;
#pragma unroll
    for (int s = 16; s > 0; s >>= 1) {
        snq += __shfl_xor_sync(0xFFFFFFFFu, snq, s);
        svq += __shfl_xor_sync(0xFFFFFFFFu, svq, s);
    }
    __shared__ float p1[32], p2[32];
    const int warp = tid >> 5, lane = tid & 31;
    if (lane == 0) { p1[warp] = snq; p2[warp] = svq; }
    __syncthreads();
    if (warp == 0) {
        float a = p1[lane], c = p2[lane];
#pragma unroll
        for (int s = 16; s > 0; s >>= 1) {
            a += __shfl_xor_sync(0xFFFFFFFFu, a, s);
            c += __shfl_xor_sync(0xFFFFFFFFu, c, s);
        }
        if (lane == 0) {
            g_denom[b] = fmaxf(a, 1.0f);
            g_vq[b] = c;
        }
    }
}

// ----------------------------------------------------------------------------
// Kernel 3: streaming 512 MB + fused GroupNorm epilogue (last block per batch)
// grid = (64 rowblocks, 64 b), block = 512 (16 warps, 1 warp/row)
// Overwrites ALL of out_C (including the region k1 used as scratch).
// ----------------------------------------------------------------------------
__global__ __launch_bounds__(512) void k3_c_update(
    const float* __restrict__ C_prev, float* __restrict__ out_C,
    const float* __restrict__ gn_w, const float* __restrict__ gn_b,
    float* __restrict__ out_h)
{
    const int b = blockIdx.y;
    const int r0 = blockIdx.x * 16;
    const int tid = threadIdx.x;

    __shared__ float sq[HH];
    __shared__ float sv[HH];
#pragma unroll
    for (int j = 0; j < 2; j++) {
        const int idx = tid + j * 512;
        sq[idx] = g_gate[0][b * HH + idx];
        sv[idx] = g_gate[2][b * HH + idx];
    }
    __syncthreads();

    const int warp = tid >> 5;
    const int lane = tid & 31;
    const int r = r0 + warp;

    const float f  = g_gate[4][b * HH + r];
    const float ik = g_gate[3][b * HH + r] * g_gate[1][b * HH + r];

    const float* __restrict__ cp = C_prev + ((size_t)b * HH + r) * HH;
    float* __restrict__ co = out_C + ((size_t)b * HH + r) * HH;

    float4 p[8];
#pragma unroll
    for (int j = 0; j < 8; j++)
        p[j] = __ldcs((const float4*)(cp + lane * 4 + j * 128));

    float dot = 0.0f;
#pragma unroll
    for (int j = 0; j < 8; j++) {
        const int c = lane * 4 + j * 128;
        float4 vv = *(const float4*)(sv + c);
        float4 qq = *(const float4*)(sq + c);
        float4 o;
        o.x = fmaf(f, p[j].x, ik * vv.x);
        o.y = fmaf(f, p[j].y, ik * vv.y);
        o.z = fmaf(f, p[j].z, ik * vv.z);
        o.w = fmaf(f, p[j].w, ik * vv.w);
        __stcs((float4*)(co + c), o);
        dot = fmaf(p[j].x, qq.x, dot);
        dot = fmaf(p[j].y, qq.y, dot);
        dot = fmaf(p[j].z, qq.z, dot);
        dot = fmaf(p[j].w, qq.w, dot);
    }
#pragma unroll
    for (int s = 16; s > 0; s >>= 1)
        dot += __shfl_xor_sync(0xFFFFFFFFu, dot, s);
    if (lane == 0) {
        g_ht[b * HH + r] = fmaf(f, dot, ik * g_vq[b]);
        __threadfence();
    }

    // ---- last-block-per-batch GroupNorm epilogue ----
    __syncthreads();
    __shared__ unsigned int s_old;
    if (tid == 0)
        s_old = atomicAdd(&g_cnt[b], 1u);
    __syncthreads();
    if (s_old != 63u) return;

    __threadfence();
    const float inv_d = 1.0f / g_denom[b];

    float xv[2];
    float s = 0.0f, s2 = 0.0f;
#pragma unroll
    for (int j = 0; j < 2; j++) {
        const int h = tid + j * 512;
        const float v = __ldcg(&g_ht[b * HH + h]) * inv_d;
        xv[j] = v;
        s += v;
        s2 = fmaf(v, v, s2);
    }
#pragma unroll
    for (int st = 16; st > 0; st >>= 1) {
        s  += __shfl_xor_sync(0xFFFFFFFFu, s, st);
        s2 += __shfl_xor_sync(0xFFFFFFFFu, s2, st);
    }
    __shared__ float p1[16], p2[16];
    __shared__ float mu_s, rstd_s;
    if (lane == 0) { p1[warp] = s; p2[warp] = s2; }
    __syncthreads();
    if (warp == 0) {
        float a = (lane < 16) ? p1[lane] : 0.0f;
        float c = (lane < 16) ? p2[lane] : 0.0f;
#pragma unroll
        for (int st = 8; st > 0; st >>= 1) {
            a += __shfl_xor_sync(0xFFFFFFFFu, a, st);
            c += __shfl_xor_sync(0xFFFFFFFFu, c, st);
        }
        if (lane == 0) {
            const float mu = a * (1.0f / HH);
            float var = c * (1.0f / HH) - mu * mu;
            var = fmaxf(var, 0.0f);
            mu_s = mu;
            rstd_s = rsqrtf(var + GN_EPS);
        }
    }
    __syncthreads();
    const float mu = mu_s, rstd = rstd_s;

#pragma unroll
    for (int j = 0; j < 2; j++) {
        const int h = tid + j * 512;
        const float norm = fmaf((xv[j] - mu) * rstd, gn_w[h], gn_b[h]);
        out_h[b * HH + h] = g_gate[5][b * HH + h] * norm;
    }
    if (tid == 0) g_cnt[b] = 0u;
}

// ----------------------------------------------------------------------------
extern "C" void kernel_launch(void* const* d_in, const int* in_sizes, int n_in,
                              void* d_out, int out_size)
{
    const float* x      = (const float*)d_in[0];
    const float* C_prev = (const float*)d_in[1];
    const float* n_prev = (const float*)d_in[2];
    const float* m_prev = (const float*)d_in[3];
    const float* Wq     = (const float*)d_in[4];
    const float* Wk     = (const float*)d_in[5];
    const float* Wv     = (const float*)d_in[6];
    const float* Wi     = (const float*)d_in[7];
    const float* bi     = (const float*)d_in[8];
    const float* Wf     = (const float*)d_in[9];
    const float* bf     = (const float*)d_in[10];
    const float* Wo     = (const float*)d_in[11];
    const float* bo     = (const float*)d_in[12];
    const float* gn_w   = (const float*)d_in[13];
    const float* gn_b   = (const float*)d_in[14];

    float* out   = (float*)d_out;
    float* out_h = out;                                   // [B,H]
    float* out_C = out_h + BB * HH;                       // [B,H,H]
    float* out_n = out_C + (size_t)BB * HH * HH;          // [B,H]
    float* out_m = out_n + BB * HH;                       // [B,H]

    // Split-K partials live in the front of out_C (6.3 MB of its 256 MB);
    // k3 fully overwrites out_C afterwards, so this is pure scratch reuse.
    float* part = out_C;

    dim3 g1(NG / NTILE, SPLITS);     // (96, 4)
    k1_gemm_gates<<<g1, 256>>>(x, Wq, Wk, Wv, Wi, Wf, Wo, part);
    k2_combine_nm<<<BB, 1024>>>(part, bi, bf, bo, n_prev, m_prev, out_n, out_m);
    dim3 g3(HH / 16, BB);
    k3_c_update<<<g3, 512>>>(C_prev, out_C, gn_w, gn_b, out_h);
}